// round 2
// baseline (speedup 1.0000x reference)
#include <cuda_runtime.h>

#define L   384
#define CD  128
#define H   4
#define DH  32
#define RTOT (L*L)   // 147456

// ---------------- scratch (static device globals; no allocation) ----------
__device__ float g_pln [RTOT*CD];   // LN(pair^T)            [n][m][c]
__device__ float g_q   [RTOT*CD];   // q scaled              [h][i][n][d]
__device__ float g_k   [RTOT*CD];   // k scaled              [h][j][n][d]
__device__ float g_v   [RTOT*CD];   // v                     [h][j][k][d]
__device__ float g_gate[RTOT*CD];   // sigmoid gate          [i][k][c]
__device__ float g_o   [RTOT*CD];   // attn@V                [i][k][h*32+d]
__device__ float g_attn[H*RTOT];    // logits/softmax        [h][i][j]
__device__ float g_bp  [H*RTOT];    // bias projection       [h][i][j]

// ---------------- LayerNorm of transposed pair -----------------------------
__global__ void ln_pair_kernel(const float* __restrict__ pair,
                               const float* __restrict__ w,
                               const float* __restrict__ b)
{
    __shared__ float ss[4], ss2[4];
    int r = blockIdx.x;            // r = n*L + m
    int n = r / L, m = r - n * L;
    int c = threadIdx.x;
    float x = pair[(m * L + n) * CD + c];
    float s = x, s2 = x * x;
#pragma unroll
    for (int o = 16; o; o >>= 1) {
        s  += __shfl_xor_sync(0xffffffffu, s,  o);
        s2 += __shfl_xor_sync(0xffffffffu, s2, o);
    }
    if ((c & 31) == 0) { ss[c >> 5] = s; ss2[c >> 5] = s2; }
    __syncthreads();
    s  = ss[0] + ss[1] + ss[2] + ss[3];
    s2 = ss2[0] + ss2[1] + ss2[2] + ss2[3];
    float mu  = s * (1.0f / CD);
    float var = s2 * (1.0f / CD) - mu * mu;
    float inv = rsqrtf(var + 1e-5f);
    g_pln[r * CD + c] = (x - mu) * inv * w[c] + b[c];
}

// ---------------- LN(bias^T) @ Wb  ->  g_bp[h][i][j] ------------------------
__global__ void bproj_kernel(const float* __restrict__ bias,
                             const float* __restrict__ w,
                             const float* __restrict__ b,
                             const float* __restrict__ Wb)
{
    __shared__ float ss[4], ss2[4];
    __shared__ float sp[4][4];
    int r = blockIdx.x;            // r = i*L + j
    int i = r / L, j = r - i * L;
    int c = threadIdx.x;
    float x = bias[(j * L + i) * CD + c];
    float s = x, s2 = x * x;
#pragma unroll
    for (int o = 16; o; o >>= 1) {
        s  += __shfl_xor_sync(0xffffffffu, s,  o);
        s2 += __shfl_xor_sync(0xffffffffu, s2, o);
    }
    if ((c & 31) == 0) { ss[c >> 5] = s; ss2[c >> 5] = s2; }
    __syncthreads();
    s  = ss[0] + ss[1] + ss[2] + ss[3];
    s2 = ss2[0] + ss2[1] + ss2[2] + ss2[3];
    float mu  = s * (1.0f / CD);
    float var = s2 * (1.0f / CD) - mu * mu;
    float inv = rsqrtf(var + 1e-5f);
    float y = (x - mu) * inv * w[c] + b[c];

    float p0 = y * Wb[c * 4 + 0];
    float p1 = y * Wb[c * 4 + 1];
    float p2 = y * Wb[c * 4 + 2];
    float p3 = y * Wb[c * 4 + 3];
#pragma unroll
    for (int o = 16; o; o >>= 1) {
        p0 += __shfl_xor_sync(0xffffffffu, p0, o);
        p1 += __shfl_xor_sync(0xffffffffu, p1, o);
        p2 += __shfl_xor_sync(0xffffffffu, p2, o);
        p3 += __shfl_xor_sync(0xffffffffu, p3, o);
    }
    if ((c & 31) == 0) {
        int wd = c >> 5;
        sp[wd][0] = p0; sp[wd][1] = p1; sp[wd][2] = p2; sp[wd][3] = p3;
    }
    __syncthreads();
    if (c < 4)
        g_bp[c * RTOT + r] = sp[0][c] + sp[1][c] + sp[2][c] + sp[3][c];
}

// ---------------- 64x64 / 4x4 fp32 tile MMA core ---------------------------
__device__ __forceinline__ void mm_tile(const float (&As)[64][36],
                                        const float (&Bs)[32][68],
                                        int ty, int tx, float (&acc)[4][4])
{
#pragma unroll
    for (int kk = 0; kk < 32; kk++) {
        float a0 = As[ty * 4 + 0][kk];
        float a1 = As[ty * 4 + 1][kk];
        float a2 = As[ty * 4 + 2][kk];
        float a3 = As[ty * 4 + 3][kk];
        float4 bv = *(const float4*)&Bs[kk][tx * 4];
        acc[0][0] += a0 * bv.x; acc[0][1] += a0 * bv.y; acc[0][2] += a0 * bv.z; acc[0][3] += a0 * bv.w;
        acc[1][0] += a1 * bv.x; acc[1][1] += a1 * bv.y; acc[1][2] += a1 * bv.z; acc[1][3] += a1 * bv.w;
        acc[2][0] += a2 * bv.x; acc[2][1] += a2 * bv.y; acc[2][2] += a2 * bv.z; acc[2][3] += a2 * bv.w;
        acc[3][0] += a3 * bv.x; acc[3][1] += a3 * bv.y; acc[3][2] += a3 * bv.z; acc[3][3] += a3 * bv.w;
    }
}

// ---------------- fused QKVG projection ------------------------------------
// C = g_pln[147456 x 128] @ W[128 x 512]; per-group scaling + layout scatter.
__global__ __launch_bounds__(256) void proj_kernel(
    const float* __restrict__ Wq, const float* __restrict__ Wk,
    const float* __restrict__ Wv, const float* __restrict__ Wg,
    const float* __restrict__ bg)
{
    __shared__ float As[64][36];
    __shared__ float Bs[32][68];
    const int tid  = threadIdx.x;
    const int tx   = tid & 15, ty = tid >> 4;
    const int row0 = blockIdx.y * 64;
    const int col0 = blockIdx.x * 64;          // 0..511
    const int grp  = col0 >> 7;                // 0=q 1=k 2=v 3=g
    const int clb  = col0 & 127;
    const float* W = (grp == 0) ? Wq : (grp == 1) ? Wk : (grp == 2) ? Wv : Wg;

    float acc[4][4] = {};
    for (int kc = 0; kc < CD; kc += 32) {
        // A: 64x32, vectorized (512 float4)
        for (int l = tid; l < 64 * 8; l += 256) {
            int rr = l >> 3, k4 = (l & 7) * 4;
            *(float4*)&As[rr][k4] =
                *(const float4*)&g_pln[(row0 + rr) * CD + kc + k4];
        }
        // B: 32x64, vectorized (512 float4)
        for (int l = tid; l < 32 * 16; l += 256) {
            int kk = l >> 4, c4 = (l & 15) * 4;
            *(float4*)&Bs[kk][c4] =
                *(const float4*)&W[(kc + kk) * 128 + clb + c4];
        }
        __syncthreads();
        mm_tile(As, Bs, ty, tx, acc);
        __syncthreads();
    }
#pragma unroll
    for (int i = 0; i < 4; i++) {
        int r = row0 + ty * 4 + i;
        int n = r / L, m = r - n * L;
#pragma unroll
        for (int j = 0; j < 4; j++) {
            int cl = clb + tx * 4 + j;
            float v = acc[i][j];
            if (grp == 3) {
                g_gate[r * CD + cl] = 1.0f / (1.0f + __expf(-(v + bg[cl])));
            } else {
                int h = cl >> 5, d = cl & 31;
                int idx = ((h * L + m) * L + n) * DH + d;
                if      (grp == 0) g_q[idx] = v * 0.17677669529663687f;   // 1/sqrt(32)
                else if (grp == 1) g_k[idx] = v * 0.051031036307982884f;  // 1/sqrt(384)
                else               g_v[idx] = v;
            }
        }
    }
}

// ---------------- logits: per-head NT GEMM 384x384, K=12288 + bias ---------
__global__ __launch_bounds__(256) void attn_kernel()
{
    __shared__ float As[64][36];
    __shared__ float Bs[32][68];
    const int tid  = threadIdx.x;
    const int tx   = tid & 15, ty = tid >> 4;
    const int h    = blockIdx.z;
    const int row0 = blockIdx.y * 64;
    const int col0 = blockIdx.x * 64;
    const float* Aq = g_q + h * RTOT * DH;
    const float* Bk = g_k + h * RTOT * DH;
    const int ldk = L * DH;  // 12288

    float acc[4][4] = {};
    for (int kc = 0; kc < ldk; kc += 32) {
        for (int l = tid; l < 64 * 8; l += 256) {
            int rr = l >> 3, k4 = (l & 7) * 4;
            *(float4*)&As[rr][k4] =
                *(const float4*)&Aq[(row0 + rr) * ldk + kc + k4];
        }
        // B transpose-load: contiguous along K in gmem, scatter into Bs
        for (int l = tid; l < 64 * 8; l += 256) {
            int cc = l >> 3, k4 = (l & 7) * 4;
            float4 t = *(const float4*)&Bk[(col0 + cc) * ldk + kc + k4];
            Bs[k4 + 0][cc] = t.x;
            Bs[k4 + 1][cc] = t.y;
            Bs[k4 + 2][cc] = t.z;
            Bs[k4 + 3][cc] = t.w;
        }
        __syncthreads();
        mm_tile(As, Bs, ty, tx, acc);
        __syncthreads();
    }
#pragma unroll
    for (int i = 0; i < 4; i++) {
        int i_ = row0 + ty * 4 + i;
#pragma unroll
        for (int j = 0; j < 4; j++) {
            int j_ = col0 + tx * 4 + j;
            int idx = (h * L + i_) * L + j_;
            g_attn[idx] = acc[i][j] + g_bp[idx];
        }
    }
}

// ---------------- softmax over j (row length 384) --------------------------
__global__ void softmax_kernel()
{
    __shared__ float rm[4], rs[4];
    int t = threadIdx.x;                       // 128 threads
    float* row = g_attn + (size_t)blockIdx.x * L;
    float v0 = row[t], v1 = row[t + 128], v2 = row[t + 256];
    float mx = fmaxf(v0, fmaxf(v1, v2));
#pragma unroll
    for (int o = 16; o; o >>= 1) mx = fmaxf(mx, __shfl_xor_sync(0xffffffffu, mx, o));
    if ((t & 31) == 0) rm[t >> 5] = mx;
    __syncthreads();
    mx = fmaxf(fmaxf(rm[0], rm[1]), fmaxf(rm[2], rm[3]));
    float e0 = __expf(v0 - mx), e1 = __expf(v1 - mx), e2 = __expf(v2 - mx);
    float s = e0 + e1 + e2;
#pragma unroll
    for (int o = 16; o; o >>= 1) s += __shfl_xor_sync(0xffffffffu, s, o);
    if ((t & 31) == 0) rs[t >> 5] = s;
    __syncthreads();
    float inv = 1.0f / (rs[0] + rs[1] + rs[2] + rs[3]);
    row[t] = e0 * inv; row[t + 128] = e1 * inv; row[t + 256] = e2 * inv;
}

// ---------------- attn @ V : per-head NN GEMM 384 x 12288, K=384 -----------
__global__ __launch_bounds__(256) void out_kernel()
{
    __shared__ float As[64][36];
    __shared__ float Bs[32][68];
    const int tid  = threadIdx.x;
    const int tx   = tid & 15, ty = tid >> 4;
    const int h    = blockIdx.z;
    const int row0 = blockIdx.y * 64;          // i
    const int col0 = blockIdx.x * 64;          // (k,d) flat
    const float* Aa = g_attn + h * RTOT;       // [384 x 384]
    const float* Bv = g_v + h * RTOT * DH;     // [384(j) x 12288(kd)]
    const int ldb = L * DH;

    float acc[4][4] = {};
    for (int kc = 0; kc < L; kc += 32) {
        for (int l = tid; l < 64 * 8; l += 256) {
            int rr = l >> 3, k4 = (l & 7) * 4;
            *(float4*)&As[rr][k4] =
                *(const float4*)&Aa[(row0 + rr) * L + kc + k4];
        }
        for (int l = tid; l < 32 * 16; l += 256) {
            int kk = l >> 4, c4 = (l & 15) * 4;
            *(float4*)&Bs[kk][c4] =
                *(const float4*)&Bv[(kc + kk) * ldb + col0 + c4];
        }
        __syncthreads();
        mm_tile(As, Bs, ty, tx, acc);
        __syncthreads();
    }
#pragma unroll
    for (int i = 0; i < 4; i++) {
        int i_ = row0 + ty * 4 + i;
#pragma unroll
        for (int j = 0; j < 4; j++) {
            int nd = col0 + tx * 4 + j;
            int k_ = nd >> 5, d = nd & 31;
            g_o[(i_ * L + k_) * CD + h * DH + d] = acc[i][j];
        }
    }
}

// ---------------- (gate*o) @ Wo + bo, store transposed ---------------------
__global__ __launch_bounds__(256) void final_kernel(const float* __restrict__ Wo,
                                                    const float* __restrict__ bo,
                                                    float* __restrict__ out)
{
    __shared__ float As[64][36];
    __shared__ float Bs[32][68];
    const int tid  = threadIdx.x;
    const int tx   = tid & 15, ty = tid >> 4;
    const int row0 = blockIdx.y * 64;          // r = i*L + k
    const int col0 = blockIdx.x * 64;          // 0 or 64

    float acc[4][4] = {};
    for (int kc = 0; kc < CD; kc += 32) {
        for (int l = tid; l < 64 * 8; l += 256) {
            int rr = l >> 3, k4 = (l & 7) * 4;
            int idx = (row0 + rr) * CD + kc + k4;
            float4 g = *(const float4*)&g_gate[idx];
            float4 o = *(const float4*)&g_o[idx];
            float4 p = make_float4(g.x * o.x, g.y * o.y, g.z * o.z, g.w * o.w);
            *(float4*)&As[rr][k4] = p;
        }
        for (int l = tid; l < 32 * 16; l += 256) {
            int kk = l >> 4, c4 = (l & 15) * 4;
            *(float4*)&Bs[kk][c4] =
                *(const float4*)&Wo[(kc + kk) * CD + col0 + c4];
        }
        __syncthreads();
        mm_tile(As, Bs, ty, tx, acc);
        __syncthreads();
    }
#pragma unroll
    for (int i = 0; i < 4; i++) {
        int r  = row0 + ty * 4 + i;
        int i_ = r / L, k_ = r - i_ * L;
#pragma unroll
        for (int j = 0; j < 4; j++) {
            int c = col0 + tx * 4 + j;
            out[(k_ * L + i_) * CD + c] = acc[i][j] + bo[c];   // transpose (0,2,1,3)
        }
    }
}

// ---------------- launch ----------------------------------------------------
extern "C" void kernel_launch(void* const* d_in, const int* in_sizes, int n_in,
                              void* d_out, int out_size)
{
    const float* pair      = (const float*)d_in[0];
    const float* bias      = (const float*)d_in[1];
    const float* ln_pair_w = (const float*)d_in[2];
    const float* ln_pair_b = (const float*)d_in[3];
    const float* ln_bias_w = (const float*)d_in[4];
    const float* ln_bias_b = (const float*)d_in[5];
    const float* Wq        = (const float*)d_in[6];
    const float* Wk        = (const float*)d_in[7];
    const float* Wv        = (const float*)d_in[8];
    const float* Wb        = (const float*)d_in[9];
    const float* Wg        = (const float*)d_in[10];
    const float* bg        = (const float*)d_in[11];
    const float* Wo        = (const float*)d_in[12];
    const float* bo        = (const float*)d_in[13];
    float* out = (float*)d_out;

    ln_pair_kernel<<<RTOT, 128>>>(pair, ln_pair_w, ln_pair_b);
    bproj_kernel  <<<RTOT, 128>>>(bias, ln_bias_w, ln_bias_b, Wb);
    proj_kernel   <<<dim3(8, RTOT / 64), 256>>>(Wq, Wk, Wv, Wg, bg);
    attn_kernel   <<<dim3(L / 64, L / 64, H), 256>>>();
    softmax_kernel<<<H * L, 128>>>();
    out_kernel    <<<dim3(L * DH / 64, L / 64, H), 256>>>();
    final_kernel  <<<dim3(2, RTOT / 64), 256>>>(Wo, bo, out);
}

// round 4
// speedup vs baseline: 2.3197x; 2.3197x over previous
#include <cuda_runtime.h>
#include <cuda_bf16.h>
#include <cstdint>

#define L    384
#define CD   128
#define H    4
#define DH   32
#define RTOT (L*L)          // 147456
#define NE   (RTOT*CD)      // 18874368
#define HR   (H*RTOT)       // 589824
#define SPAD 40             // bf16 elems per smem tile row (80B stride, conflict-free)
#define KSPL 4              // K-split for logits GEMM
#define KSL  (L*DH/KSPL)    // 3072

typedef __nv_bfloat16 bf16;

// ---------------- scratch (static device globals) --------------------------
__device__ bf16  g_pln_hi[NE], g_pln_lo[NE];     // LN(pair^T)  [n*L+m][c]
__device__ bf16  g_q_hi[NE],   g_q_lo[NE];       // [h][i][n*32+d]   (K-contig)
__device__ bf16  g_k_hi[NE],   g_k_lo[NE];       // [h][j][n*32+d]   (K-contig)
__device__ bf16  g_vT_hi[NE],  g_vT_lo[NE];      // [h][k*32+d][j]   (K-contig)
__device__ bf16  g_p_hi[HR],   g_p_lo[HR];       // softmax probs [h][i][j]
__device__ bf16  g_WT_hi[512*128], g_WT_lo[512*128];  // [cl_all][c]
__device__ bf16  g_WoT_hi[128*128], g_WoT_lo[128*128];
__device__ float g_gate[NE];                     // [n*L+m][c]  (== [i*L+k][c])
__device__ float g_o[NE];                        // [i*L+k][h*32+d]
__device__ float g_attnp[KSPL*HR];               // partial logits
__device__ float g_bp[HR];                       // bias projection [h][i][j]

// ---------------- helpers ---------------------------------------------------
__device__ __forceinline__ void bsplit(float x, bf16& h, bf16& l) {
    h = __float2bfloat16(x);
    l = __float2bfloat16(x - __bfloat162float(h));
}

__device__ __forceinline__ void ldsm4(uint32_t r[4], const bf16* p) {
    uint32_t s = (uint32_t)__cvta_generic_to_shared((void*)p);
    asm volatile("ldmatrix.sync.aligned.m8n8.x4.shared.b16 {%0,%1,%2,%3}, [%4];\n"
        : "=r"(r[0]), "=r"(r[1]), "=r"(r[2]), "=r"(r[3]) : "r"(s));
}

__device__ __forceinline__ void mma_bf16(float (&d)[4], const uint32_t a[4],
                                         uint32_t b0, uint32_t b1) {
    asm volatile("mma.sync.aligned.m16n8k16.row.col.f32.bf16.bf16.f32 "
        "{%0,%1,%2,%3}, {%4,%5,%6,%7}, {%8,%9}, {%0,%1,%2,%3};\n"
        : "+f"(d[0]), "+f"(d[1]), "+f"(d[2]), "+f"(d[3])
        : "r"(a[0]), "r"(a[1]), "r"(a[2]), "r"(a[3]), "r"(b0), "r"(b1));
}

// 3-term split MMA over one 32-wide k-chunk. Warp tile 32x32 at (wm, wn).
__device__ __forceinline__ void gemm_chunk(
    const bf16* Ah, const bf16* Al, const bf16* Bh, const bf16* Bl,
    int wm, int wn, int lane, float (&acc)[2][4][4])
{
    const int arow  = (lane & 7) + ((lane >> 3) & 1) * 8;
    const int akoff = (lane >> 4) * 8;
    const int brow  = (lane & 7) + ((lane >> 4) & 1) * 8;
    const int bkoff = ((lane >> 3) & 1) * 8;
#pragma unroll
    for (int ks = 0; ks < 2; ks++) {
        uint32_t ah[2][4], al[2][4], bh[2][4], bl[2][4];
#pragma unroll
        for (int mi = 0; mi < 2; mi++) {
            int off = (wm*32 + mi*16 + arow) * SPAD + ks*16 + akoff;
            ldsm4(ah[mi], Ah + off);
            ldsm4(al[mi], Al + off);
        }
#pragma unroll
        for (int nb = 0; nb < 2; nb++) {
            int off = (wn*32 + nb*16 + brow) * SPAD + ks*16 + bkoff;
            ldsm4(bh[nb], Bh + off);
            ldsm4(bl[nb], Bl + off);
        }
#pragma unroll
        for (int mi = 0; mi < 2; mi++)
#pragma unroll
            for (int ni = 0; ni < 4; ni++) {
                int nb = ni >> 1, s = (ni & 1) * 2;
                mma_bf16(acc[mi][ni], ah[mi], bh[nb][s], bh[nb][s+1]);  // hi*hi
                mma_bf16(acc[mi][ni], ah[mi], bl[nb][s], bl[nb][s+1]);  // hi*lo
                mma_bf16(acc[mi][ni], al[mi], bh[nb][s], bh[nb][s+1]);  // lo*hi
            }
    }
}

// tile loaders: [row][K] gmem (K contiguous) -> padded smem tile, uint4 copies
__device__ __forceinline__ void load_A128(bf16* dh, bf16* dl,
    const bf16* sh, const bf16* sl, int row0, int ld, int k0, int tid)
{
#pragma unroll
    for (int l = tid; l < 512; l += 256) {
        int row = l >> 2, seg = (l & 3) * 8;
        int g = (row0 + row) * ld + k0 + seg;
        *(uint4*)&dh[row*SPAD + seg] = *(const uint4*)&sh[g];
        *(uint4*)&dl[row*SPAD + seg] = *(const uint4*)&sl[g];
    }
}
__device__ __forceinline__ void load_B64(bf16* dh, bf16* dl,
    const bf16* sh, const bf16* sl, int row0, int ld, int k0, int tid)
{
    int row = tid >> 2, seg = (tid & 3) * 8;
    int g = (row0 + row) * ld + k0 + seg;
    *(uint4*)&dh[row*SPAD + seg] = *(const uint4*)&sh[g];
    *(uint4*)&dl[row*SPAD + seg] = *(const uint4*)&sl[g];
}

// ---------------- weight prep: transpose + split ---------------------------
__global__ void prep_weights(const float* __restrict__ Wq, const float* __restrict__ Wk,
                             const float* __restrict__ Wv, const float* __restrict__ Wg,
                             const float* __restrict__ Wo)
{
    int idx = blockIdx.x * 256 + threadIdx.x;
    if (idx < 512*128) {
        int cl = idx >> 7, c = idx & 127;
        int grp = cl >> 7, cll = cl & 127;
        const float* W = (grp == 0) ? Wq : (grp == 1) ? Wk : (grp == 2) ? Wv : Wg;
        bsplit(W[c * 128 + cll], g_WT_hi[idx], g_WT_lo[idx]);
    } else if (idx < 512*128 + 128*128) {
        int j = idx - 512*128;
        int cl = j >> 7, c = j & 127;
        bsplit(Wo[c * 128 + cl], g_WoT_hi[j], g_WoT_lo[j]);
    }
}

// ---------------- LayerNorm of transposed pair -> hi/lo --------------------
__global__ void ln_pair_kernel(const float* __restrict__ pair,
                               const float* __restrict__ w,
                               const float* __restrict__ b)
{
    __shared__ float ss[4], ss2[4];
    int r = blockIdx.x;            // r = n*L + m
    int n = r / L, m = r - n * L;
    int c = threadIdx.x;
    float x = pair[(m * L + n) * CD + c];
    float s = x, s2 = x * x;
#pragma unroll
    for (int o = 16; o; o >>= 1) {
        s  += __shfl_xor_sync(0xffffffffu, s,  o);
        s2 += __shfl_xor_sync(0xffffffffu, s2, o);
    }
    if ((c & 31) == 0) { ss[c >> 5] = s; ss2[c >> 5] = s2; }
    __syncthreads();
    s  = ss[0] + ss[1] + ss[2] + ss[3];
    s2 = ss2[0] + ss2[1] + ss2[2] + ss2[3];
    float mu  = s * (1.0f / CD);
    float var = s2 * (1.0f / CD) - mu * mu;
    float inv = rsqrtf(var + 1e-5f);
    float y = (x - mu) * inv * w[c] + b[c];
    bsplit(y, g_pln_hi[r * CD + c], g_pln_lo[r * CD + c]);
}

// ---------------- LN(bias^T) @ Wb -> g_bp[h][i][j] -------------------------
__global__ void bproj_kernel(const float* __restrict__ bias,
                             const float* __restrict__ w,
                             const float* __restrict__ b,
                             const float* __restrict__ Wb)
{
    __shared__ float ss[4], ss2[4];
    __shared__ float sp[4][4];
    int r = blockIdx.x;            // r = i*L + j
    int i = r / L, j = r - i * L;
    int c = threadIdx.x;
    float x = bias[(j * L + i) * CD + c];
    float s = x, s2 = x * x;
#pragma unroll
    for (int o = 16; o; o >>= 1) {
        s  += __shfl_xor_sync(0xffffffffu, s,  o);
        s2 += __shfl_xor_sync(0xffffffffu, s2, o);
    }
    if ((c & 31) == 0) { ss[c >> 5] = s; ss2[c >> 5] = s2; }
    __syncthreads();
    s  = ss[0] + ss[1] + ss[2] + ss[3];
    s2 = ss2[0] + ss2[1] + ss2[2] + ss2[3];
    float mu  = s * (1.0f / CD);
    float var = s2 * (1.0f / CD) - mu * mu;
    float inv = rsqrtf(var + 1e-5f);
    float y = (x - mu) * inv * w[c] + b[c];

    float p0 = y * Wb[c*4+0], p1 = y * Wb[c*4+1], p2 = y * Wb[c*4+2], p3 = y * Wb[c*4+3];
#pragma unroll
    for (int o = 16; o; o >>= 1) {
        p0 += __shfl_xor_sync(0xffffffffu, p0, o);
        p1 += __shfl_xor_sync(0xffffffffu, p1, o);
        p2 += __shfl_xor_sync(0xffffffffu, p2, o);
        p3 += __shfl_xor_sync(0xffffffffu, p3, o);
    }
    if ((c & 31) == 0) {
        int wd = c >> 5;
        sp[wd][0] = p0; sp[wd][1] = p1; sp[wd][2] = p2; sp[wd][3] = p3;
    }
    __syncthreads();
    if (c < 4)
        g_bp[c * RTOT + r] = sp[0][c] + sp[1][c] + sp[2][c] + sp[3][c];
}

// ---------------- fused QKVG projection (tensor core) ----------------------
__global__ __launch_bounds__(256) void proj_kernel(const float* __restrict__ bg)
{
    __shared__ bf16 Ah[128*SPAD], Al[128*SPAD], Bh[64*SPAD], Bl[64*SPAD];
    const int tid = threadIdx.x, lane = tid & 31, wid = tid >> 5;
    const int wm = wid & 3, wn = wid >> 2;
    const int row0 = blockIdx.y * 128, col0 = blockIdx.x * 64;
    const int grp = col0 >> 7;

    float acc[2][4][4] = {};
    for (int kc = 0; kc < CD; kc += 32) {
        load_A128(Ah, Al, g_pln_hi, g_pln_lo, row0, CD, kc, tid);
        load_B64 (Bh, Bl, g_WT_hi,  g_WT_lo,  col0, CD, kc, tid);
        __syncthreads();
        gemm_chunk(Ah, Al, Bh, Bl, wm, wn, lane, acc);
        __syncthreads();
    }
#pragma unroll
    for (int mi = 0; mi < 2; mi++)
#pragma unroll
    for (int ni = 0; ni < 4; ni++)
#pragma unroll
    for (int p = 0; p < 4; p++) {
        int R  = row0 + wm*32 + mi*16 + (lane >> 2) + (p >> 1) * 8;
        int ca = col0 + wn*32 + ni*8 + (lane & 3) * 2 + (p & 1);
        int n = R / L, m = R - n * L;
        int cl = ca & 127;
        float v = acc[mi][ni][p];
        if (grp == 3) {
            g_gate[R * CD + cl] = 1.0f / (1.0f + __expf(-(v + bg[cl])));
        } else {
            int h = cl >> 5, d = cl & 31;
            if (grp == 0) {
                int idx = ((h*L + m)*L + n)*DH + d;
                bsplit(v * 0.17677669529663687f, g_q_hi[idx], g_q_lo[idx]);
            } else if (grp == 1) {
                int idx = ((h*L + m)*L + n)*DH + d;
                bsplit(v * 0.051031036307982884f, g_k_hi[idx], g_k_lo[idx]);
            } else {
                int idx = ((h*L + n)*DH + d)*L + m;   // vT[h][k*32+d][j]
                bsplit(v, g_vT_hi[idx], g_vT_lo[idx]);
            }
        }
    }
}

// ---------------- logits: per-head NT GEMM, K-split x4 ---------------------
__global__ __launch_bounds__(256) void attn_kernel()
{
    __shared__ bf16 Ah[128*SPAD], Al[128*SPAD], Bh[64*SPAD], Bl[64*SPAD];
    const int tid = threadIdx.x, lane = tid & 31, wid = tid >> 5;
    const int wm = wid & 3, wn = wid >> 2;
    const int h = blockIdx.z >> 2, slice = blockIdx.z & 3;
    const int row0 = blockIdx.y * 128, col0 = blockIdx.x * 64;
    const int base = h * (L * L * DH);
    const int ldk = L * DH;        // 12288
    const int k0 = slice * KSL;

    float acc[2][4][4] = {};
    for (int kc = 0; kc < KSL; kc += 32) {
        load_A128(Ah, Al, g_q_hi + base, g_q_lo + base, row0, ldk, k0 + kc, tid);
        load_B64 (Bh, Bl, g_k_hi + base, g_k_lo + base, col0, ldk, k0 + kc, tid);
        __syncthreads();
        gemm_chunk(Ah, Al, Bh, Bl, wm, wn, lane, acc);
        __syncthreads();
    }
#pragma unroll
    for (int mi = 0; mi < 2; mi++)
#pragma unroll
    for (int ni = 0; ni < 4; ni++)
#pragma unroll
    for (int p = 0; p < 4; p++) {
        int i_ = row0 + wm*32 + mi*16 + (lane >> 2) + (p >> 1) * 8;
        int j_ = col0 + wn*32 + ni*8 + (lane & 3) * 2 + (p & 1);
        g_attnp[slice * HR + (h*L + i_)*L + j_] = acc[mi][ni][p];
    }
}

// ---------------- softmax over j + bias, writes probs hi/lo ----------------
__global__ void softmax_kernel()
{
    __shared__ float rm[4], rs[4];
    int row = blockIdx.x;          // h*L + i
    int t = threadIdx.x;           // 128
    int base = row * L;
    float v0, v1, v2;
    {
        int j0 = base + t, j1 = j0 + 128, j2 = j0 + 256;
        v0 = g_bp[j0] + g_attnp[j0] + g_attnp[HR + j0] + g_attnp[2*HR + j0] + g_attnp[3*HR + j0];
        v1 = g_bp[j1] + g_attnp[j1] + g_attnp[HR + j1] + g_attnp[2*HR + j1] + g_attnp[3*HR + j1];
        v2 = g_bp[j2] + g_attnp[j2] + g_attnp[HR + j2] + g_attnp[2*HR + j2] + g_attnp[3*HR + j2];
    }
    float mx = fmaxf(v0, fmaxf(v1, v2));
#pragma unroll
    for (int o = 16; o; o >>= 1) mx = fmaxf(mx, __shfl_xor_sync(0xffffffffu, mx, o));
    if ((t & 31) == 0) rm[t >> 5] = mx;
    __syncthreads();
    mx = fmaxf(fmaxf(rm[0], rm[1]), fmaxf(rm[2], rm[3]));
    float e0 = __expf(v0 - mx), e1 = __expf(v1 - mx), e2 = __expf(v2 - mx);
    float s = e0 + e1 + e2;
#pragma unroll
    for (int o = 16; o; o >>= 1) s += __shfl_xor_sync(0xffffffffu, s, o);
    if ((t & 31) == 0) rs[t >> 5] = s;
    __syncthreads();
    float inv = 1.0f / (rs[0] + rs[1] + rs[2] + rs[3]);
    bsplit(e0 * inv, g_p_hi[base + t      ], g_p_lo[base + t      ]);
    bsplit(e1 * inv, g_p_hi[base + t + 128], g_p_lo[base + t + 128]);
    bsplit(e2 * inv, g_p_hi[base + t + 256], g_p_lo[base + t + 256]);
}

// ---------------- attn @ V : per-head NT-layout GEMM -----------------------
__global__ __launch_bounds__(256) void out_kernel()
{
    __shared__ bf16 Ah[128*SPAD], Al[128*SPAD], Bh[64*SPAD], Bl[64*SPAD];
    const int tid = threadIdx.x, lane = tid & 31, wid = tid >> 5;
    const int wm = wid & 3, wn = wid >> 2;
    const int h = blockIdx.z;
    const int row0 = blockIdx.y * 128;     // i
    const int col0 = blockIdx.x * 64;      // nd = k*32 + d
    const int abase = h * RTOT;
    const int bbase = h * (L * DH * L);

    float acc[2][4][4] = {};
    for (int kc = 0; kc < L; kc += 32) {
        load_A128(Ah, Al, g_p_hi  + abase, g_p_lo  + abase, row0, L, kc, tid);
        load_B64 (Bh, Bl, g_vT_hi + bbase, g_vT_lo + bbase, col0, L, kc, tid);
        __syncthreads();
        gemm_chunk(Ah, Al, Bh, Bl, wm, wn, lane, acc);
        __syncthreads();
    }
#pragma unroll
    for (int mi = 0; mi < 2; mi++)
#pragma unroll
    for (int ni = 0; ni < 4; ni++)
#pragma unroll
    for (int p = 0; p < 4; p++) {
        int i_ = row0 + wm*32 + mi*16 + (lane >> 2) + (p >> 1) * 8;
        int nd = col0 + wn*32 + ni*8 + (lane & 3) * 2 + (p & 1);
        int k_ = nd >> 5, d = nd & 31;
        g_o[(i_*L + k_)*CD + h*DH + d] = acc[mi][ni][p];
    }
}

// ---------------- (gate*o) @ Wo + bo, transposed store ---------------------
__global__ __launch_bounds__(256) void final_kernel(const float* __restrict__ bo,
                                                    float* __restrict__ out)
{
    __shared__ bf16 Ah[128*SPAD], Al[128*SPAD], Bh[64*SPAD], Bl[64*SPAD];
    const int tid = threadIdx.x, lane = tid & 31, wid = tid >> 5;
    const int wm = wid & 3, wn = wid >> 2;
    const int row0 = blockIdx.y * 128;     // r = i*L + k
    const int col0 = blockIdx.x * 64;      // c

    float acc[2][4][4] = {};
    for (int kc = 0; kc < CD; kc += 32) {
        // A: gate*o computed on the fly, split to hi/lo
#pragma unroll
        for (int l = tid; l < 1024; l += 256) {
            int row = l >> 3, sg = (l & 7) * 4;
            int g = (row0 + row) * CD + kc + sg;
            float4 gv = *(const float4*)&g_gate[g];
            float4 ov = *(const float4*)&g_o[g];
            float p0 = gv.x * ov.x, p1 = gv.y * ov.y, p2 = gv.z * ov.z, p3 = gv.w * ov.w;
            bf16 h0,l0,h1,l1,h2,l2,h3,l3;
            bsplit(p0,h0,l0); bsplit(p1,h1,l1); bsplit(p2,h2,l2); bsplit(p3,h3,l3);
            int o_ = row*SPAD + sg;
            *(__nv_bfloat162*)&Ah[o_    ] = __nv_bfloat162(h0, h1);
            *(__nv_bfloat162*)&Ah[o_ + 2] = __nv_bfloat162(h2, h3);
            *(__nv_bfloat162*)&Al[o_    ] = __nv_bfloat162(l0, l1);
            *(__nv_bfloat162*)&Al[o_ + 2] = __nv_bfloat162(l2, l3);
        }
        load_B64(Bh, Bl, g_WoT_hi, g_WoT_lo, col0, CD, kc, tid);
        __syncthreads();
        gemm_chunk(Ah, Al, Bh, Bl, wm, wn, lane, acc);
        __syncthreads();
    }
#pragma unroll
    for (int mi = 0; mi < 2; mi++)
#pragma unroll
    for (int ni = 0; ni < 4; ni++)
#pragma unroll
    for (int p = 0; p < 4; p++) {
        int R = row0 + wm*32 + mi*16 + (lane >> 2) + (p >> 1) * 8;
        int c = col0 + wn*32 + ni*8 + (lane & 3) * 2 + (p & 1);
        int i_ = R / L, k_ = R - i_ * L;
        out[(k_*L + i_)*CD + c] = acc[mi][ni][p] + bo[c];
    }
}

// ---------------- launch ----------------------------------------------------
extern "C" void kernel_launch(void* const* d_in, const int* in_sizes, int n_in,
                              void* d_out, int out_size)
{
    const float* pair      = (const float*)d_in[0];
    const float* bias      = (const float*)d_in[1];
    const float* ln_pair_w = (const float*)d_in[2];
    const float* ln_pair_b = (const float*)d_in[3];
    const float* ln_bias_w = (const float*)d_in[4];
    const float* ln_bias_b = (const float*)d_in[5];
    const float* Wq        = (const float*)d_in[6];
    const float* Wk        = (const float*)d_in[7];
    const float* Wv        = (const float*)d_in[8];
    const float* Wb        = (const float*)d_in[9];
    const float* Wg        = (const float*)d_in[10];
    const float* bg        = (const float*)d_in[11];
    const float* Wo        = (const float*)d_in[12];
    const float* bo        = (const float*)d_in[13];
    float* out = (float*)d_out;

    prep_weights  <<<320, 256>>>(Wq, Wk, Wv, Wg, Wo);
    ln_pair_kernel<<<RTOT, 128>>>(pair, ln_pair_w, ln_pair_b);
    bproj_kernel  <<<RTOT, 128>>>(bias, ln_bias_w, ln_bias_b, Wb);
    proj_kernel   <<<dim3(8, RTOT/128), 256>>>(bg);
    attn_kernel   <<<dim3(L/64, L/128, H*KSPL), 256>>>();
    softmax_kernel<<<H*L, 128>>>();
    out_kernel    <<<dim3(L*DH/64, L/128, H), 256>>>();
    final_kernel  <<<dim3(2, RTOT/128), 256>>>(bo, out);
}

// round 6
// speedup vs baseline: 2.8849x; 1.2436x over previous
#include <cuda_runtime.h>
#include <cuda_bf16.h>
#include <cstdint>

#define L    384
#define CD   128
#define H    4
#define DH   32
#define RTOT (L*L)          // 147456
#define NE   (RTOT*CD)      // 18874368
#define HR   (H*RTOT)       // 589824
#define SPAD 40             // bf16 elems per smem row (80B stride, conflict-free for ldmatrix)
#define KSPL 4              // K-split for logits GEMM
#define KSL  (L*DH/KSPL)    // 3072
#define ASZ  (128*SPAD)     // 5120 elems
#define BSZ  (64*SPAD)      // 2560 elems
#define SMEM_BYTES ((4*ASZ + 4*BSZ)*2)   // 61440 B (double-buffered Ah/Al/Bh/Bl)

typedef __nv_bfloat16 bf16;

// ---------------- scratch (static device globals) --------------------------
__device__ bf16  g_pln_hi[NE], g_pln_lo[NE];     // LN(pair^T)  [n*L+m][c]
__device__ bf16  g_q_hi[NE],   g_q_lo[NE];       // [n*L+i][h*32+d]  natural
__device__ bf16  g_k_hi[NE],   g_k_lo[NE];       // [n*L+j][h*32+d]  natural
__device__ bf16  g_v_hi[NE],   g_v_lo[NE];       // [k*L+j][h*32+d]  natural
__device__ bf16  g_vT_hi[NE],  g_vT_lo[NE];      // [h][k*32+d][j]   transposed
__device__ bf16  g_p_hi[HR],   g_p_lo[HR];       // softmax probs [h][i][j]
__device__ bf16  g_WT_hi[512*128], g_WT_lo[512*128];  // [cl_all][c]
__device__ bf16  g_WoT_hi[128*128], g_WoT_lo[128*128];
__device__ float g_gate[NE];                     // [i*L+k][c]
__device__ float g_o[NE];                        // [i*L+k][h*32+d]
__device__ float g_attnp[KSPL*HR];               // partial logits
__device__ float g_bp[HR];                       // bias projection [h][i][j]

// ---------------- helpers ---------------------------------------------------
__device__ __forceinline__ void bsplit(float x, bf16& h, bf16& l) {
    h = __float2bfloat16(x);
    l = __float2bfloat16(x - __bfloat162float(h));
}

__device__ __forceinline__ void cp16(void* s, const void* g) {
    uint32_t sa = (uint32_t)__cvta_generic_to_shared(s);
    asm volatile("cp.async.ca.shared.global [%0], [%1], 16;\n" :: "r"(sa), "l"(g));
}
__device__ __forceinline__ void cp_commit() { asm volatile("cp.async.commit_group;\n"); }
__device__ __forceinline__ void cp_wait0()  { asm volatile("cp.async.wait_group 0;\n"); }

__device__ __forceinline__ void ldsm4(uint32_t r[4], const bf16* p) {
    uint32_t s = (uint32_t)__cvta_generic_to_shared((void*)p);
    asm volatile("ldmatrix.sync.aligned.m8n8.x4.shared.b16 {%0,%1,%2,%3}, [%4];\n"
        : "=r"(r[0]), "=r"(r[1]), "=r"(r[2]), "=r"(r[3]) : "r"(s));
}

__device__ __forceinline__ void mma_bf16(float (&d)[4], const uint32_t a[4],
                                         uint32_t b0, uint32_t b1) {
    asm volatile("mma.sync.aligned.m16n8k16.row.col.f32.bf16.bf16.f32 "
        "{%0,%1,%2,%3}, {%4,%5,%6,%7}, {%8,%9}, {%0,%1,%2,%3};\n"
        : "+f"(d[0]), "+f"(d[1]), "+f"(d[2]), "+f"(d[3])
        : "r"(a[0]), "r"(a[1]), "r"(a[2]), "r"(a[3]), "r"(b0), "r"(b1));
}

// 3-term split MMA over one 32-wide k-chunk. Warp tile 32x32 at (wm, wn).
__device__ __forceinline__ void gemm_chunk(
    const bf16* Ah, const bf16* Al, const bf16* Bh, const bf16* Bl,
    int wm, int wn, int lane, float (&acc)[2][4][4])
{
    const int arow  = (lane & 7) + ((lane >> 3) & 1) * 8;
    const int akoff = (lane >> 4) * 8;
    const int brow  = (lane & 7) + ((lane >> 4) & 1) * 8;
    const int bkoff = ((lane >> 3) & 1) * 8;
#pragma unroll
    for (int ks = 0; ks < 2; ks++) {
        uint32_t ah[2][4], al[2][4], bh[2][4], bl[2][4];
#pragma unroll
        for (int mi = 0; mi < 2; mi++) {
            int off = (wm*32 + mi*16 + arow) * SPAD + ks*16 + akoff;
            ldsm4(ah[mi], Ah + off);
            ldsm4(al[mi], Al + off);
        }
#pragma unroll
        for (int nb = 0; nb < 2; nb++) {
            int off = (wn*32 + nb*16 + brow) * SPAD + ks*16 + bkoff;
            ldsm4(bh[nb], Bh + off);
            ldsm4(bl[nb], Bl + off);
        }
#pragma unroll
        for (int mi = 0; mi < 2; mi++)
#pragma unroll
            for (int ni = 0; ni < 4; ni++) {
                int nb = ni >> 1, s = (ni & 1) * 2;
                mma_bf16(acc[mi][ni], ah[mi], bh[nb][s], bh[nb][s+1]);  // hi*hi
                mma_bf16(acc[mi][ni], ah[mi], bl[nb][s], bl[nb][s+1]);  // hi*lo
                mma_bf16(acc[mi][ni], al[mi], bh[nb][s], bh[nb][s+1]);  // lo*hi
            }
    }
}

// ---------------- weight prep: transpose + split ---------------------------
__global__ void prep_weights(const float* __restrict__ Wq, const float* __restrict__ Wk,
                             const float* __restrict__ Wv, const float* __restrict__ Wg,
                             const float* __restrict__ Wo)
{
    int idx = blockIdx.x * 256 + threadIdx.x;
    if (idx < 512*128) {
        int cl = idx >> 7, c = idx & 127;
        int grp = cl >> 7, cll = cl & 127;
        const float* W = (grp == 0) ? Wq : (grp == 1) ? Wk : (grp == 2) ? Wv : Wg;
        bsplit(W[c * 128 + cll], g_WT_hi[idx], g_WT_lo[idx]);
    } else if (idx < 512*128 + 128*128) {
        int j = idx - 512*128;
        int cl = j >> 7, c = j & 127;
        bsplit(Wo[c * 128 + cl], g_WoT_hi[j], g_WoT_lo[j]);
    }
}

// ---------------- LayerNorm of transposed pair -> hi/lo --------------------
__global__ void ln_pair_kernel(const float* __restrict__ pair,
                               const float* __restrict__ w,
                               const float* __restrict__ b)
{
    __shared__ float ss[4], ss2[4];
    int r = blockIdx.x;            // r = n*L + m
    int n = r / L, m = r - n * L;
    int c = threadIdx.x;
    float x = pair[(m * L + n) * CD + c];
    float s = x, s2 = x * x;
#pragma unroll
    for (int o = 16; o; o >>= 1) {
        s  += __shfl_xor_sync(0xffffffffu, s,  o);
        s2 += __shfl_xor_sync(0xffffffffu, s2, o);
    }
    if ((c & 31) == 0) { ss[c >> 5] = s; ss2[c >> 5] = s2; }
    __syncthreads();
    s  = ss[0] + ss[1] + ss[2] + ss[3];
    s2 = ss2[0] + ss2[1] + ss2[2] + ss2[3];
    float mu  = s * (1.0f / CD);
    float var = s2 * (1.0f / CD) - mu * mu;
    float inv = rsqrtf(var + 1e-5f);
    float y = (x - mu) * inv * w[c] + b[c];
    bsplit(y, g_pln_hi[r * CD + c], g_pln_lo[r * CD + c]);
}

// ---------------- LN(bias^T) @ Wb -> g_bp[h][i][j] -------------------------
__global__ void bproj_kernel(const float* __restrict__ bias,
                             const float* __restrict__ w,
                             const float* __restrict__ b,
                             const float* __restrict__ Wb)
{
    __shared__ float ss[4], ss2[4];
    __shared__ float sp[4][4];
    int r = blockIdx.x;            // r = i*L + j
    int i = r / L, j = r - i * L;
    int c = threadIdx.x;
    float x = bias[(j * L + i) * CD + c];
    float s = x, s2 = x * x;
#pragma unroll
    for (int o = 16; o; o >>= 1) {
        s  += __shfl_xor_sync(0xffffffffu, s,  o);
        s2 += __shfl_xor_sync(0xffffffffu, s2, o);
    }
    if ((c & 31) == 0) { ss[c >> 5] = s; ss2[c >> 5] = s2; }
    __syncthreads();
    s  = ss[0] + ss[1] + ss[2] + ss[3];
    s2 = ss2[0] + ss2[1] + ss2[2] + ss2[3];
    float mu  = s * (1.0f / CD);
    float var = s2 * (1.0f / CD) - mu * mu;
    float inv = rsqrtf(var + 1e-5f);
    float y = (x - mu) * inv * w[c] + b[c];

    float p0 = y * Wb[c*4+0], p1 = y * Wb[c*4+1], p2 = y * Wb[c*4+2], p3 = y * Wb[c*4+3];
#pragma unroll
    for (int o = 16; o; o >>= 1) {
        p0 += __shfl_xor_sync(0xffffffffu, p0, o);
        p1 += __shfl_xor_sync(0xffffffffu, p1, o);
        p2 += __shfl_xor_sync(0xffffffffu, p2, o);
        p3 += __shfl_xor_sync(0xffffffffu, p3, o);
    }
    if ((c & 31) == 0) {
        int wd = c >> 5;
        sp[wd][0] = p0; sp[wd][1] = p1; sp[wd][2] = p2; sp[wd][3] = p3;
    }
    __syncthreads();
    if (c < 4)
        g_bp[c * RTOT + r] = sp[0][c] + sp[1][c] + sp[2][c] + sp[3][c];
}

// ---------------- fused QKVG projection (tensor core, cp.async 2-stage) ----
__global__ __launch_bounds__(256) void proj_kernel(const float* __restrict__ bg)
{
    extern __shared__ bf16 sm[];
    bf16* AH[2] = { sm,           sm + ASZ };
    bf16* AL[2] = { sm + 2*ASZ,   sm + 3*ASZ };
    bf16* BH[2] = { sm + 4*ASZ,         sm + 4*ASZ + BSZ };
    bf16* BL[2] = { sm + 4*ASZ + 2*BSZ, sm + 4*ASZ + 3*BSZ };
    const int tid = threadIdx.x, lane = tid & 31, wid = tid >> 5;
    const int wm = wid & 3, wn = wid >> 2;
    const int row0 = blockIdx.y * 128, col0 = blockIdx.x * 64;
    const int grp = col0 >> 7;

    auto load = [&](int kc, int s) {
#pragma unroll
        for (int l = tid; l < 512; l += 256) {
            int row = l >> 2, seg = (l & 3) * 8;
            int g = (row0 + row) * CD + kc + seg;
            cp16(AH[s] + row*SPAD + seg, g_pln_hi + g);
            cp16(AL[s] + row*SPAD + seg, g_pln_lo + g);
        }
        {
            int row = tid >> 2, seg = (tid & 3) * 8;
            int g = (col0 + row) * CD + kc + seg;
            cp16(BH[s] + row*SPAD + seg, g_WT_hi + g);
            cp16(BL[s] + row*SPAD + seg, g_WT_lo + g);
        }
        cp_commit();
    };

    float acc[2][4][4] = {};
    load(0, 0);
    for (int c = 0; c < 4; c++) {
        cp_wait0(); __syncthreads();
        if (c < 3) load((c+1)*32, (c+1)&1);
        gemm_chunk(AH[c&1], AL[c&1], BH[c&1], BL[c&1], wm, wn, lane, acc);
    }

    const float qs = 0.17677669529663687f, ks = 0.051031036307982884f;
#pragma unroll
    for (int mi = 0; mi < 2; mi++)
#pragma unroll
    for (int ni = 0; ni < 4; ni++)
#pragma unroll
    for (int hf = 0; hf < 2; hf++) {
        int R  = row0 + wm*32 + mi*16 + (lane >> 2) + hf*8;
        int ca = col0 + wn*32 + ni*8 + (lane & 3)*2;
        int cl = ca & 127;
        float v0 = acc[mi][ni][hf*2], v1 = acc[mi][ni][hf*2+1];
        int o = R * CD + cl;
        if (grp == 3) {
            float2 gv;
            gv.x = 1.0f / (1.0f + __expf(-(v0 + bg[cl])));
            gv.y = 1.0f / (1.0f + __expf(-(v1 + bg[cl+1])));
            *(float2*)&g_gate[o] = gv;
        } else {
            bf16 *dh, *dl; float sc;
            if (grp == 0)      { dh = g_q_hi; dl = g_q_lo; sc = qs; }
            else if (grp == 1) { dh = g_k_hi; dl = g_k_lo; sc = ks; }
            else               { dh = g_v_hi; dl = g_v_lo; sc = 1.0f; }
            v0 *= sc; v1 *= sc;
            bf16 h0, l0, h1, l1;
            bsplit(v0, h0, l0); bsplit(v1, h1, l1);
            *(__nv_bfloat162*)&dh[o] = __nv_bfloat162(h0, h1);
            *(__nv_bfloat162*)&dl[o] = __nv_bfloat162(l0, l1);
        }
    }
}

// ---------------- V transpose: [k*L+j][h*32+d] -> [h][k*32+d][j] -----------
__global__ void transp_v()
{
    __shared__ bf16 th[32*40], tl[32*40];
    const int jt = blockIdx.x;   // 0..11
    const int k  = blockIdx.y;   // 0..383
    const int h  = blockIdx.z;
    const int tid = threadIdx.x; // 128
    const int j0 = jt * 32;
    {
        int j = tid >> 2, seg = (tid & 3) * 8;
        int sw = seg ^ ((j >> 3) << 3);             // XOR swizzle (8-elem blocks)
        int g = (k * L + j0 + j) * CD + h * 32 + seg;
        *(uint4*)&th[j*40 + sw] = *(const uint4*)&g_v_hi[g];
        *(uint4*)&tl[j*40 + sw] = *(const uint4*)&g_v_lo[g];
    }
    __syncthreads();
    {
        int d = tid >> 2, segj = (tid & 3) * 8;
        uint4 uh, ul;
        bf16* ph = (bf16*)&uh; bf16* pl = (bf16*)&ul;
#pragma unroll
        for (int t = 0; t < 8; t++) {
            int j = segj + t;
            int col = ((d >> 3) ^ (j >> 3)) * 8 + (d & 7);
            ph[t] = th[j*40 + col];
            pl[t] = tl[j*40 + col];
        }
        int g = ((h * L + k) * DH + d) * L + j0 + segj;
        *(uint4*)&g_vT_hi[g] = uh;
        *(uint4*)&g_vT_lo[g] = ul;
    }
}

// ---------------- logits: per-head NT GEMM, K-split x4, cp.async -----------
__global__ __launch_bounds__(256) void attn_kernel()
{
    extern __shared__ bf16 sm[];
    bf16* AH[2] = { sm,           sm + ASZ };
    bf16* AL[2] = { sm + 2*ASZ,   sm + 3*ASZ };
    bf16* BH[2] = { sm + 4*ASZ,         sm + 4*ASZ + BSZ };
    bf16* BL[2] = { sm + 4*ASZ + 2*BSZ, sm + 4*ASZ + 3*BSZ };
    const int tid = threadIdx.x, lane = tid & 31, wid = tid >> 5;
    const int wm = wid & 3, wn = wid >> 2;
    const int h = blockIdx.z >> 2, slice = blockIdx.z & 3;
    const int row0 = blockIdx.y * 128, col0 = blockIdx.x * 64;
    const int n0 = slice * (KSL / DH);   // 96 n-values per slice
    const int cb = h * 32;

    auto load = [&](int ci, int s) {
        int nb = (n0 + ci) * L;
#pragma unroll
        for (int l = tid; l < 512; l += 256) {
            int row = l >> 2, seg = (l & 3) * 8;
            int g = (nb + row0 + row) * CD + cb + seg;
            cp16(AH[s] + row*SPAD + seg, g_q_hi + g);
            cp16(AL[s] + row*SPAD + seg, g_q_lo + g);
        }
        {
            int row = tid >> 2, seg = (tid & 3) * 8;
            int g = (nb + col0 + row) * CD + cb + seg;
            cp16(BH[s] + row*SPAD + seg, g_k_hi + g);
            cp16(BL[s] + row*SPAD + seg, g_k_lo + g);
        }
        cp_commit();
    };

    float acc[2][4][4] = {};
    load(0, 0);
    for (int c = 0; c < 96; c++) {
        cp_wait0(); __syncthreads();
        if (c < 95) load(c+1, (c+1)&1);
        gemm_chunk(AH[c&1], AL[c&1], BH[c&1], BL[c&1], wm, wn, lane, acc);
    }
#pragma unroll
    for (int mi = 0; mi < 2; mi++)
#pragma unroll
    for (int ni = 0; ni < 4; ni++)
#pragma unroll
    for (int hf = 0; hf < 2; hf++) {
        int i_ = row0 + wm*32 + mi*16 + (lane >> 2) + hf*8;
        int j_ = col0 + wn*32 + ni*8 + (lane & 3)*2;
        int idx = slice * HR + (h*L + i_)*L + j_;
        *(float2*)&g_attnp[idx] = make_float2(acc[mi][ni][hf*2], acc[mi][ni][hf*2+1]);
    }
}

// ---------------- softmax over j + bias, writes probs hi/lo ----------------
__global__ void softmax_kernel()
{
    __shared__ float rm[4], rs[4];
    int row = blockIdx.x;          // h*L + i
    int t = threadIdx.x;           // 128
    int base = row * L;
    float v0, v1, v2;
    {
        int j0 = base + t, j1 = j0 + 128, j2 = j0 + 256;
        v0 = g_bp[j0] + g_attnp[j0] + g_attnp[HR + j0] + g_attnp[2*HR + j0] + g_attnp[3*HR + j0];
        v1 = g_bp[j1] + g_attnp[j1] + g_attnp[HR + j1] + g_attnp[2*HR + j1] + g_attnp[3*HR + j1];
        v2 = g_bp[j2] + g_attnp[j2] + g_attnp[HR + j2] + g_attnp[2*HR + j2] + g_attnp[3*HR + j2];
    }
    float mx = fmaxf(v0, fmaxf(v1, v2));
#pragma unroll
    for (int o = 16; o; o >>= 1) mx = fmaxf(mx, __shfl_xor_sync(0xffffffffu, mx, o));
    if ((t & 31) == 0) rm[t >> 5] = mx;
    __syncthreads();
    mx = fmaxf(fmaxf(rm[0], rm[1]), fmaxf(rm[2], rm[3]));
    float e0 = __expf(v0 - mx), e1 = __expf(v1 - mx), e2 = __expf(v2 - mx);
    float s = e0 + e1 + e2;
#pragma unroll
    for (int o = 16; o; o >>= 1) s += __shfl_xor_sync(0xffffffffu, s, o);
    if ((t & 31) == 0) rs[t >> 5] = s;
    __syncthreads();
    float inv = 1.0f / (rs[0] + rs[1] + rs[2] + rs[3]);
    bsplit(e0 * inv, g_p_hi[base + t      ], g_p_lo[base + t      ]);
    bsplit(e1 * inv, g_p_hi[base + t + 128], g_p_lo[base + t + 128]);
    bsplit(e2 * inv, g_p_hi[base + t + 256], g_p_lo[base + t + 256]);
}

// ---------------- attn @ V : per-head GEMM over j, cp.async ----------------
__global__ __launch_bounds__(256) void out_kernel()
{
    extern __shared__ bf16 sm[];
    bf16* AH[2] = { sm,           sm + ASZ };
    bf16* AL[2] = { sm + 2*ASZ,   sm + 3*ASZ };
    bf16* BH[2] = { sm + 4*ASZ,         sm + 4*ASZ + BSZ };
    bf16* BL[2] = { sm + 4*ASZ + 2*BSZ, sm + 4*ASZ + 3*BSZ };
    const int tid = threadIdx.x, lane = tid & 31, wid = tid >> 5;
    const int wm = wid & 3, wn = wid >> 2;
    const int h = blockIdx.z;
    const int row0 = blockIdx.y * 128;     // i
    const int col0 = blockIdx.x * 64;      // nd = k*32 + d
    const int abase = h * RTOT;
    const int bbase = h * L * DH;          // vT row base

    auto load = [&](int kc, int s) {
#pragma unroll
        for (int l = tid; l < 512; l += 256) {
            int row = l >> 2, seg = (l & 3) * 8;
            int g = abase + (row0 + row) * L + kc + seg;
            cp16(AH[s] + row*SPAD + seg, g_p_hi + g);
            cp16(AL[s] + row*SPAD + seg, g_p_lo + g);
        }
        {
            int row = tid >> 2, seg = (tid & 3) * 8;
            int g = (bbase + col0 + row) * L + kc + seg;
            cp16(BH[s] + row*SPAD + seg, g_vT_hi + g);
            cp16(BL[s] + row*SPAD + seg, g_vT_lo + g);
        }
        cp_commit();
    };

    float acc[2][4][4] = {};
    load(0, 0);
    for (int c = 0; c < 12; c++) {
        cp_wait0(); __syncthreads();
        if (c < 11) load((c+1)*32, (c+1)&1);
        gemm_chunk(AH[c&1], AL[c&1], BH[c&1], BL[c&1], wm, wn, lane, acc);
    }
#pragma unroll
    for (int mi = 0; mi < 2; mi++)
#pragma unroll
    for (int ni = 0; ni < 4; ni++)
#pragma unroll
    for (int hf = 0; hf < 2; hf++) {
        int i_ = row0 + wm*32 + mi*16 + (lane >> 2) + hf*8;
        int nd = col0 + wn*32 + ni*8 + (lane & 3)*2;
        int k_ = nd >> 5, d = nd & 31;
        *(float2*)&g_o[(i_*L + k_)*CD + h*DH + d] =
            make_float2(acc[mi][ni][hf*2], acc[mi][ni][hf*2+1]);
    }
}

// ---------------- (gate*o) @ Wo + bo, transposed store ---------------------
__global__ __launch_bounds__(256) void final_kernel(const float* __restrict__ bo,
                                                    float* __restrict__ out)
{
    __shared__ bf16 Ah[128*SPAD], Al[128*SPAD], Bh[64*SPAD], Bl[64*SPAD];
    const int tid = threadIdx.x, lane = tid & 31, wid = tid >> 5;
    const int wm = wid & 3, wn = wid >> 2;
    const int row0 = blockIdx.y * 128;     // r = i*L + k
    const int col0 = blockIdx.x * 64;      // c

    float acc[2][4][4] = {};
    for (int kc = 0; kc < CD; kc += 32) {
#pragma unroll
        for (int l = tid; l < 1024; l += 256) {
            int row = l >> 3, sg = (l & 7) * 4;
            int g = (row0 + row) * CD + kc + sg;
            float4 gv = *(const float4*)&g_gate[g];
            float4 ov = *(const float4*)&g_o[g];
            float p0 = gv.x * ov.x, p1 = gv.y * ov.y, p2 = gv.z * ov.z, p3 = gv.w * ov.w;
            bf16 h0,l0,h1,l1,h2,l2,h3,l3;
            bsplit(p0,h0,l0); bsplit(p1,h1,l1); bsplit(p2,h2,l2); bsplit(p3,h3,l3);
            int o_ = row*SPAD + sg;
            *(__nv_bfloat162*)&Ah[o_    ] = __nv_bfloat162(h0, h1);
            *(__nv_bfloat162*)&Ah[o_ + 2] = __nv_bfloat162(h2, h3);
            *(__nv_bfloat162*)&Al[o_    ] = __nv_bfloat162(l0, l1);
            *(__nv_bfloat162*)&Al[o_ + 2] = __nv_bfloat162(l2, l3);
        }
        {
            int row = tid >> 2, seg = (tid & 3) * 8;
            int g = (col0 + row) * CD + kc + seg;
            *(uint4*)&Bh[row*SPAD + seg] = *(const uint4*)&g_WoT_hi[g];
            *(uint4*)&Bl[row*SPAD + seg] = *(const uint4*)&g_WoT_lo[g];
        }
        __syncthreads();
        gemm_chunk(Ah, Al, Bh, Bl, wm, wn, lane, acc);
        __syncthreads();
    }
#pragma unroll
    for (int mi = 0; mi < 2; mi++)
#pragma unroll
    for (int ni = 0; ni < 4; ni++)
#pragma unroll
    for (int hf = 0; hf < 2; hf++) {
        int R = row0 + wm*32 + mi*16 + (lane >> 2) + hf*8;
        int c = col0 + wn*32 + ni*8 + (lane & 3)*2;
        int i_ = R / L, k_ = R - i_ * L;
        *(float2*)&out[(k_*L + i_)*CD + c] =
            make_float2(acc[mi][ni][hf*2] + bo[c], acc[mi][ni][hf*2+1] + bo[c+1]);
    }
}

// ---------------- launch ----------------------------------------------------
extern "C" void kernel_launch(void* const* d_in, const int* in_sizes, int n_in,
                              void* d_out, int out_size)
{
    const float* pair      = (const float*)d_in[0];
    const float* bias      = (const float*)d_in[1];
    const float* ln_pair_w = (const float*)d_in[2];
    const float* ln_pair_b = (const float*)d_in[3];
    const float* ln_bias_w = (const float*)d_in[4];
    const float* ln_bias_b = (const float*)d_in[5];
    const float* Wq        = (const float*)d_in[6];
    const float* Wk        = (const float*)d_in[7];
    const float* Wv        = (const float*)d_in[8];
    const float* Wb        = (const float*)d_in[9];
    const float* Wg        = (const float*)d_in[10];
    const float* bg        = (const float*)d_in[11];
    const float* Wo        = (const float*)d_in[12];
    const float* bo        = (const float*)d_in[13];
    float* out = (float*)d_out;

    cudaFuncSetAttribute(proj_kernel, cudaFuncAttributeMaxDynamicSharedMemorySize, SMEM_BYTES);
    cudaFuncSetAttribute(attn_kernel, cudaFuncAttributeMaxDynamicSharedMemorySize, SMEM_BYTES);
    cudaFuncSetAttribute(out_kernel,  cudaFuncAttributeMaxDynamicSharedMemorySize, SMEM_BYTES);

    prep_weights  <<<320, 256>>>(Wq, Wk, Wv, Wg, Wo);
    ln_pair_kernel<<<RTOT, 128>>>(pair, ln_pair_w, ln_pair_b);
    bproj_kernel  <<<RTOT, 128>>>(bias, ln_bias_w, ln_bias_b, Wb);
    proj_kernel   <<<dim3(8, RTOT/128), 256, SMEM_BYTES>>>(bg);
    transp_v      <<<dim3(L/32, L, H), 128>>>();
    attn_kernel   <<<dim3(L/64, L/128, H*KSPL), 256, SMEM_BYTES>>>();
    softmax_kernel<<<H*L, 128>>>();
    out_kernel    <<<dim3(L*DH/64, L/128, H), 256, SMEM_BYTES>>>();
    final_kernel  <<<dim3(2, RTOT/128), 256>>>(bo, out);
}

// round 9
// speedup vs baseline: 3.2149x; 1.1144x over previous
#include <cuda_runtime.h>
#include <cuda_bf16.h>
#include <cstdint>

#define L    384
#define CD   128
#define H    4
#define DH   32
#define RTOT (L*L)          // 147456
#define NE   (RTOT*CD)      // 18874368
#define HR   (H*RTOT)       // 589824
#define SPAD 40             // bf16 elems per smem row (80B stride, conflict-free)
#define KSPL 4              // K-split for logits GEMM
#define TSZ  (128*SPAD)     // 5120 elems per tile (A or B, 128 rows)
#define SMEM_BYTES (8*TSZ*2)   // 81920 B : AH/AL/BH/BL x 2 stages

typedef __nv_bfloat16 bf16;

// ---------------- scratch (static device globals) --------------------------
__device__ bf16  g_pln_hi[NE], g_pln_lo[NE];     // LN(pair^T)  [n*L+m][c]
__device__ bf16  g_q_hi[NE],   g_q_lo[NE];       // [n*L+i][h*32+d]
__device__ bf16  g_k_hi[NE],   g_k_lo[NE];       // [n*L+j][h*32+d]
__device__ bf16  g_v_hi[NE],   g_v_lo[NE];       // [k*L+j][h*32+d]
__device__ bf16  g_vT_hi[NE],  g_vT_lo[NE];      // [h][k*32+d][j]
__device__ bf16  g_p_hi[HR],   g_p_lo[HR];       // softmax probs [h][i][j]
__device__ bf16  g_WT_hi[512*128], g_WT_lo[512*128];  // [cl_all][c]
__device__ bf16  g_WoT_hi[128*128], g_WoT_lo[128*128];
__device__ float g_gate[NE];                     // [i*L+k][c]
__device__ float g_o[NE];                        // [i*L+k][h*32+d]
__device__ float g_attnp[KSPL*HR];               // partial logits
__device__ float g_bp[HR];                       // bias projection [h][i][j]

// ---------------- helpers ---------------------------------------------------
__device__ __forceinline__ void bsplit(float x, bf16& h, bf16& l) {
    h = __float2bfloat16(x);
    l = __float2bfloat16(x - __bfloat162float(h));
}

__device__ __forceinline__ void cp16(void* s, const void* g) {
    uint32_t sa = (uint32_t)__cvta_generic_to_shared(s);
    asm volatile("cp.async.ca.shared.global [%0], [%1], 16;\n" :: "r"(sa), "l"(g));
}
__device__ __forceinline__ void cp_commit() { asm volatile("cp.async.commit_group;\n"); }
__device__ __forceinline__ void cp_wait0()  { asm volatile("cp.async.wait_group 0;\n"); }

__device__ __forceinline__ void ldsm4(uint32_t r[4], const bf16* p) {
    uint32_t s = (uint32_t)__cvta_generic_to_shared((void*)p);
    asm volatile("ldmatrix.sync.aligned.m8n8.x4.shared.b16 {%0,%1,%2,%3}, [%4];\n"
        : "=r"(r[0]), "=r"(r[1]), "=r"(r[2]), "=r"(r[3]) : "r"(s));
}

__device__ __forceinline__ void mma_bf16(float (&d)[4], const uint32_t a[4],
                                         uint32_t b0, uint32_t b1) {
    asm volatile("mma.sync.aligned.m16n8k16.row.col.f32.bf16.bf16.f32 "
        "{%0,%1,%2,%3}, {%4,%5,%6,%7}, {%8,%9}, {%0,%1,%2,%3};\n"
        : "+f"(d[0]), "+f"(d[1]), "+f"(d[2]), "+f"(d[3])
        : "r"(a[0]), "r"(a[1]), "r"(a[2]), "r"(a[3]), "r"(b0), "r"(b1));
}

// 3-term split MMA, warp tile 64x32 at (wm, wn), one 32-wide k-chunk.
// Per 16-k step: 4 B-ldsm + 8 A-ldsm feed 48 HMMA  (4:1 MMA:LDSM).
__device__ __forceinline__ void gemm_chunk(
    const bf16* Ah, const bf16* Al, const bf16* Bh, const bf16* Bl,
    int wm, int wn, int lane, float (&acc)[4][4][4])
{
    const int arow  = (lane & 7) + ((lane >> 3) & 1) * 8;
    const int akoff = (lane >> 4) * 8;
    const int brow  = (lane & 7) + ((lane >> 4) & 1) * 8;
    const int bkoff = ((lane >> 3) & 1) * 8;
#pragma unroll
    for (int ks = 0; ks < 2; ks++) {
        uint32_t bh[2][4], bl[2][4];
#pragma unroll
        for (int nb = 0; nb < 2; nb++) {
            int off = (wn*32 + nb*16 + brow) * SPAD + ks*16 + bkoff;
            ldsm4(bh[nb], Bh + off);
            ldsm4(bl[nb], Bl + off);
        }
#pragma unroll
        for (int mi = 0; mi < 4; mi++) {
            uint32_t ah[4], al[4];
            int off = (wm*64 + mi*16 + arow) * SPAD + ks*16 + akoff;
            ldsm4(ah, Ah + off);
            ldsm4(al, Al + off);
#pragma unroll
            for (int ni = 0; ni < 4; ni++) {
                int nb = ni >> 1, s = (ni & 1) * 2;
                mma_bf16(acc[mi][ni], ah, bh[nb][s], bh[nb][s+1]);  // hi*hi
                mma_bf16(acc[mi][ni], ah, bl[nb][s], bl[nb][s+1]);  // hi*lo
                mma_bf16(acc[mi][ni], al, bh[nb][s], bh[nb][s+1]);  // lo*hi
            }
        }
    }
}

// ---------------- weight prep: transpose + split ---------------------------
__global__ void prep_weights(const float* __restrict__ Wq, const float* __restrict__ Wk,
                             const float* __restrict__ Wv, const float* __restrict__ Wg,
                             const float* __restrict__ Wo)
{
    int idx = blockIdx.x * 256 + threadIdx.x;
    if (idx < 512*128) {
        int cl = idx >> 7, c = idx & 127;
        int grp = cl >> 7, cll = cl & 127;
        const float* W = (grp == 0) ? Wq : (grp == 1) ? Wk : (grp == 2) ? Wv : Wg;
        bsplit(W[c * 128 + cll], g_WT_hi[idx], g_WT_lo[idx]);
    } else if (idx < 512*128 + 128*128) {
        int j = idx - 512*128;
        int cl = j >> 7, c = j & 127;
        bsplit(Wo[c * 128 + cl], g_WoT_hi[j], g_WoT_lo[j]);
    }
}

// ---------------- LayerNorm of transposed pair -> hi/lo --------------------
__global__ void ln_pair_kernel(const float* __restrict__ pair,
                               const float* __restrict__ w,
                               const float* __restrict__ b)
{
    __shared__ float ss[4], ss2[4];
    int r = blockIdx.x;            // r = n*L + m
    int n = r / L, m = r - n * L;
    int c = threadIdx.x;
    float x = pair[(m * L + n) * CD + c];
    float s = x, s2 = x * x;
#pragma unroll
    for (int o = 16; o; o >>= 1) {
        s  += __shfl_xor_sync(0xffffffffu, s,  o);
        s2 += __shfl_xor_sync(0xffffffffu, s2, o);
    }
    if ((c & 31) == 0) { ss[c >> 5] = s; ss2[c >> 5] = s2; }
    __syncthreads();
    s  = ss[0] + ss[1] + ss[2] + ss[3];
    s2 = ss2[0] + ss2[1] + ss2[2] + ss2[3];
    float mu  = s * (1.0f / CD);
    float var = s2 * (1.0f / CD) - mu * mu;
    float inv = rsqrtf(var + 1e-5f);
    float y = (x - mu) * inv * w[c] + b[c];
    bsplit(y, g_pln_hi[r * CD + c], g_pln_lo[r * CD + c]);
}

// ---------------- LN(bias^T) @ Wb -> g_bp[h][i][j] -------------------------
__global__ void bproj_kernel(const float* __restrict__ bias,
                             const float* __restrict__ w,
                             const float* __restrict__ b,
                             const float* __restrict__ Wb)
{
    __shared__ float ss[4], ss2[4];
    __shared__ float sp[4][4];
    int r = blockIdx.x;            // r = i*L + j
    int i = r / L, j = r - i * L;
    int c = threadIdx.x;
    float x = bias[(j * L + i) * CD + c];
    float s = x, s2 = x * x;
#pragma unroll
    for (int o = 16; o; o >>= 1) {
        s  += __shfl_xor_sync(0xffffffffu, s,  o);
        s2 += __shfl_xor_sync(0xffffffffu, s2, o);
    }
    if ((c & 31) == 0) { ss[c >> 5] = s; ss2[c >> 5] = s2; }
    __syncthreads();
    s  = ss[0] + ss[1] + ss[2] + ss[3];
    s2 = ss2[0] + ss2[1] + ss2[2] + ss2[3];
    float mu  = s * (1.0f / CD);
    float var = s2 * (1.0f / CD) - mu * mu;
    float inv = rsqrtf(var + 1e-5f);
    float y = (x - mu) * inv * w[c] + b[c];

    float p0 = y * Wb[c*4+0], p1 = y * Wb[c*4+1], p2 = y * Wb[c*4+2], p3 = y * Wb[c*4+3];
#pragma unroll
    for (int o = 16; o; o >>= 1) {
        p0 += __shfl_xor_sync(0xffffffffu, p0, o);
        p1 += __shfl_xor_sync(0xffffffffu, p1, o);
        p2 += __shfl_xor_sync(0xffffffffu, p2, o);
        p3 += __shfl_xor_sync(0xffffffffu, p3, o);
    }
    if ((c & 31) == 0) {
        int wd = c >> 5;
        sp[wd][0] = p0; sp[wd][1] = p1; sp[wd][2] = p2; sp[wd][3] = p3;
    }
    __syncthreads();
    if (c < 4)
        g_bp[c * RTOT + r] = sp[0][c] + sp[1][c] + sp[2][c] + sp[3][c];
}

// 128-row tile fill via cp.async (A or B), K-contig source
#define LOAD_TILE(DH_, DL_, SH_, SL_, ROWB, LD, K0)                      \
    {                                                                    \
        _Pragma("unroll")                                                \
        for (int l = tid; l < 512; l += 256) {                           \
            int row = l >> 2, seg = (l & 3) * 8;                         \
            int g = (ROWB + row) * (LD) + (K0) + seg;                    \
            cp16((DH_) + row*SPAD + seg, (SH_) + g);                     \
            cp16((DL_) + row*SPAD + seg, (SL_) + g);                     \
        }                                                                \
    }

// ---------------- fused QKVG projection ------------------------------------
__global__ __launch_bounds__(256) void proj_kernel(const float* __restrict__ bg)
{
    extern __shared__ bf16 sm[];
    bf16* AH[2] = { sm,         sm + TSZ };
    bf16* AL[2] = { sm + 2*TSZ, sm + 3*TSZ };
    bf16* BH[2] = { sm + 4*TSZ, sm + 5*TSZ };
    bf16* BL[2] = { sm + 6*TSZ, sm + 7*TSZ };
    const int tid = threadIdx.x, lane = tid & 31, wid = tid >> 5;
    const int wn = wid & 3, wm = wid >> 2;
    const int row0 = blockIdx.y * 128;
    const int grp  = blockIdx.x;             // one weight group per x-block
    const int colw0 = grp * 128;

    auto load = [&](int kc, int s) {
        LOAD_TILE(AH[s], AL[s], g_pln_hi, g_pln_lo, row0, CD, kc);
        LOAD_TILE(BH[s], BL[s], g_WT_hi,  g_WT_lo,  colw0, CD, kc);
        cp_commit();
    };

    float acc[4][4][4] = {};
    load(0, 0);
    for (int c = 0; c < 4; c++) {
        cp_wait0(); __syncthreads();
        if (c < 3) load((c+1)*32, (c+1)&1);
        gemm_chunk(AH[c&1], AL[c&1], BH[c&1], BL[c&1], wm, wn, lane, acc);
    }

    const float qs = 0.17677669529663687f, ks = 0.051031036307982884f;
#pragma unroll
    for (int mi = 0; mi < 4; mi++)
#pragma unroll
    for (int ni = 0; ni < 4; ni++)
#pragma unroll
    for (int hf = 0; hf < 2; hf++) {
        int R  = row0 + wm*64 + mi*16 + (lane >> 2) + hf*8;
        int cl = wn*32 + ni*8 + (lane & 3)*2;
        float v0 = acc[mi][ni][hf*2], v1 = acc[mi][ni][hf*2+1];
        int o = R * CD + cl;
        if (grp == 3) {
            float2 gv;
            gv.x = 1.0f / (1.0f + __expf(-(v0 + bg[cl])));
            gv.y = 1.0f / (1.0f + __expf(-(v1 + bg[cl+1])));
            *(float2*)&g_gate[o] = gv;
        } else {
            bf16 *dh, *dl; float sc;
            if (grp == 0)      { dh = g_q_hi; dl = g_q_lo; sc = qs; }
            else if (grp == 1) { dh = g_k_hi; dl = g_k_lo; sc = ks; }
            else               { dh = g_v_hi; dl = g_v_lo; sc = 1.0f; }
            v0 *= sc; v1 *= sc;
            bf16 h0, l0, h1, l1;
            bsplit(v0, h0, l0); bsplit(v1, h1, l1);
            *(__nv_bfloat162*)&dh[o] = __nv_bfloat162(h0, h1);
            *(__nv_bfloat162*)&dl[o] = __nv_bfloat162(l0, l1);
        }
    }
}

// ---------------- V transpose: [k*L+j][h*32+d] -> [h][k*32+d][j] -----------
__global__ void transp_v()
{
    __shared__ bf16 th[32*40], tl[32*40];
    const int jt = blockIdx.x;   // 0..11
    const int k  = blockIdx.y;   // 0..383
    const int h  = blockIdx.z;
    const int tid = threadIdx.x; // 128
    const int j0 = jt * 32;
    {
        int j = tid >> 2, seg = (tid & 3) * 8;
        int sw = seg ^ ((j >> 3) << 3);             // XOR swizzle (8-elem blocks)
        int g = (k * L + j0 + j) * CD + h * 32 + seg;
        *(uint4*)&th[j*40 + sw] = *(const uint4*)&g_v_hi[g];
        *(uint4*)&tl[j*40 + sw] = *(const uint4*)&g_v_lo[g];
    }
    __syncthreads();
    {
        int d = tid >> 2, segj = (tid & 3) * 8;
        uint4 uh, ul;
        bf16* ph = (bf16*)&uh; bf16* pl = (bf16*)&ul;
#pragma unroll
        for (int t = 0; t < 8; t++) {
            int j = segj + t;
            int col = ((d >> 3) ^ (j >> 3)) * 8 + (d & 7);
            ph[t] = th[j*40 + col];
            pl[t] = tl[j*40 + col];
        }
        int g = ((h * L + k) * DH + d) * L + j0 + segj;
        *(uint4*)&g_vT_hi[g] = uh;
        *(uint4*)&g_vT_lo[g] = ul;
    }
}

// ---------------- logits: per-head NT GEMM, K-split x4 ---------------------
__global__ __launch_bounds__(256) void attn_kernel()
{
    extern __shared__ bf16 sm[];
    bf16* AH[2] = { sm,         sm + TSZ };
    bf16* AL[2] = { sm + 2*TSZ, sm + 3*TSZ };
    bf16* BH[2] = { sm + 4*TSZ, sm + 5*TSZ };
    bf16* BL[2] = { sm + 6*TSZ, sm + 7*TSZ };
    const int tid = threadIdx.x, lane = tid & 31, wid = tid >> 5;
    const int wn = wid & 3, wm = wid >> 2;
    const int h = blockIdx.z >> 2, slice = blockIdx.z & 3;
    const int row0 = blockIdx.y * 128, col0 = blockIdx.x * 128;
    const int n0 = slice * 96;
    const int cb = h * 32;

    auto load = [&](int ci, int s) {
        int nb = (n0 + ci) * L;
        LOAD_TILE(AH[s], AL[s], g_q_hi, g_q_lo, nb + row0, CD, cb);
        LOAD_TILE(BH[s], BL[s], g_k_hi, g_k_lo, nb + col0, CD, cb);
        cp_commit();
    };

    float acc[4][4][4] = {};
    load(0, 0);
    for (int c = 0; c < 96; c++) {
        cp_wait0(); __syncthreads();
        if (c < 95) load(c+1, (c+1)&1);
        gemm_chunk(AH[c&1], AL[c&1], BH[c&1], BL[c&1], wm, wn, lane, acc);
    }
#pragma unroll
    for (int mi = 0; mi < 4; mi++)
#pragma unroll
    for (int ni = 0; ni < 4; ni++)
#pragma unroll
    for (int hf = 0; hf < 2; hf++) {
        int i_ = row0 + wm*64 + mi*16 + (lane >> 2) + hf*8;
        int j_ = col0 + wn*32 + ni*8 + (lane & 3)*2;
        int idx = slice * HR + (h*L + i_)*L + j_;
        *(float2*)&g_attnp[idx] = make_float2(acc[mi][ni][hf*2], acc[mi][ni][hf*2+1]);
    }
}

// ---------------- softmax over j + bias, writes probs hi/lo ----------------
__global__ void softmax_kernel()
{
    __shared__ float rm[4], rs[4];
    int row = blockIdx.x;          // h*L + i
    int t = threadIdx.x;           // 128
    int base = row * L;
    float v0, v1, v2;
    {
        int j0 = base + t, j1 = j0 + 128, j2 = j0 + 256;
        v0 = g_bp[j0] + g_attnp[j0] + g_attnp[HR + j0] + g_attnp[2*HR + j0] + g_attnp[3*HR + j0];
        v1 = g_bp[j1] + g_attnp[j1] + g_attnp[HR + j1] + g_attnp[2*HR + j1] + g_attnp[3*HR + j1];
        v2 = g_bp[j2] + g_attnp[j2] + g_attnp[HR + j2] + g_attnp[2*HR + j2] + g_attnp[3*HR + j2];
    }
    float mx = fmaxf(v0, fmaxf(v1, v2));
#pragma unroll
    for (int o = 16; o; o >>= 1) mx = fmaxf(mx, __shfl_xor_sync(0xffffffffu, mx, o));
    if ((t & 31) == 0) rm[t >> 5] = mx;
    __syncthreads();
    mx = fmaxf(fmaxf(rm[0], rm[1]), fmaxf(rm[2], rm[3]));
    float e0 = __expf(v0 - mx), e1 = __expf(v1 - mx), e2 = __expf(v2 - mx);
    float s = e0 + e1 + e2;
#pragma unroll
    for (int o = 16; o; o >>= 1) s += __shfl_xor_sync(0xffffffffu, s, o);
    if ((t & 31) == 0) rs[t >> 5] = s;
    __syncthreads();
    float inv = 1.0f / (rs[0] + rs[1] + rs[2] + rs[3]);
    bsplit(e0 * inv, g_p_hi[base + t      ], g_p_lo[base + t      ]);
    bsplit(e1 * inv, g_p_hi[base + t + 128], g_p_lo[base + t + 128]);
    bsplit(e2 * inv, g_p_hi[base + t + 256], g_p_lo[base + t + 256]);
}

// ---------------- attn @ V : per-head GEMM over j --------------------------
__global__ __launch_bounds__(256) void out_kernel()
{
    extern __shared__ bf16 sm[];
    bf16* AH[2] = { sm,         sm + TSZ };
    bf16* AL[2] = { sm + 2*TSZ, sm + 3*TSZ };
    bf16* BH[2] = { sm + 4*TSZ, sm + 5*TSZ };
    bf16* BL[2] = { sm + 6*TSZ, sm + 7*TSZ };
    const int tid = threadIdx.x, lane = tid & 31, wid = tid >> 5;
    const int wn = wid & 3, wm = wid >> 2;
    const int h = blockIdx.z;
    const int row0 = blockIdx.y * 128;     // i
    const int col0 = blockIdx.x * 128;     // nd = k*32 + d
    const int abase = h * RTOT;
    const int bbase = h * L * DH;          // vT row base

    auto load = [&](int kc, int s) {
        LOAD_TILE(AH[s], AL[s], g_p_hi + abase,  g_p_lo + abase,  row0,         L, kc);
        LOAD_TILE(BH[s], BL[s], g_vT_hi + (size_t)bbase * L, g_vT_lo + (size_t)bbase * L, col0, L, kc);
        cp_commit();
    };

    float acc[4][4][4] = {};
    load(0, 0);
    for (int c = 0; c < 12; c++) {
        cp_wait0(); __syncthreads();
        if (c < 11) load((c+1)*32, (c+1)&1);
        gemm_chunk(AH[c&1], AL[c&1], BH[c&1], BL[c&1], wm, wn, lane, acc);
    }
#pragma unroll
    for (int mi = 0; mi < 4; mi++)
#pragma unroll
    for (int ni = 0; ni < 4; ni++)
#pragma unroll
    for (int hf = 0; hf < 2; hf++) {
        int i_ = row0 + wm*64 + mi*16 + (lane >> 2) + hf*8;
        int nd = col0 + wn*32 + ni*8 + (lane & 3)*2;
        int k_ = nd >> 5, d = nd & 31;
        *(float2*)&g_o[(i_*L + k_)*CD + h*DH + d] =
            make_float2(acc[mi][ni][hf*2], acc[mi][ni][hf*2+1]);
    }
}

// ---------------- (gate*o) @ Wo + bo, transposed store ---------------------
__global__ __launch_bounds__(256) void final_kernel(const float* __restrict__ bo,
                                                    float* __restrict__ out)
{
    __shared__ bf16 Ah[TSZ], Al[TSZ], Bh[TSZ], Bl[TSZ];
    const int tid = threadIdx.x, lane = tid & 31, wid = tid >> 5;
    const int wn = wid & 3, wm = wid >> 2;
    const int row0 = blockIdx.y * 128;     // r = i*L + k

    float acc[4][4][4] = {};
    for (int kc = 0; kc < CD; kc += 32) {
#pragma unroll
        for (int l = tid; l < 1024; l += 256) {
            int row = l >> 3, sg = (l & 7) * 4;
            int g = (row0 + row) * CD + kc + sg;
            float4 gv = *(const float4*)&g_gate[g];
            float4 ov = *(const float4*)&g_o[g];
            float p0 = gv.x * ov.x, p1 = gv.y * ov.y, p2 = gv.z * ov.z, p3 = gv.w * ov.w;
            bf16 h0,l0,h1,l1,h2,l2,h3,l3;
            bsplit(p0,h0,l0); bsplit(p1,h1,l1); bsplit(p2,h2,l2); bsplit(p3,h3,l3);
            int o_ = row*SPAD + sg;
            *(__nv_bfloat162*)&Ah[o_    ] = __nv_bfloat162(h0, h1);
            *(__nv_bfloat162*)&Ah[o_ + 2] = __nv_bfloat162(h2, h3);
            *(__nv_bfloat162*)&Al[o_    ] = __nv_bfloat162(l0, l1);
            *(__nv_bfloat162*)&Al[o_ + 2] = __nv_bfloat162(l2, l3);
        }
#pragma unroll
        for (int l = tid; l < 512; l += 256) {
            int row = l >> 2, seg = (l & 3) * 8;
            int g = row * CD + kc + seg;
            *(uint4*)&Bh[row*SPAD + seg] = *(const uint4*)&g_WoT_hi[g];
            *(uint4*)&Bl[row*SPAD + seg] = *(const uint4*)&g_WoT_lo[g];
        }
        __syncthreads();
        gemm_chunk(Ah, Al, Bh, Bl, wm, wn, lane, acc);
        __syncthreads();
    }
#pragma unroll
    for (int mi = 0; mi < 4; mi++)
#pragma unroll
    for (int ni = 0; ni < 4; ni++)
#pragma unroll
    for (int hf = 0; hf < 2; hf++) {
        int R = row0 + wm*64 + mi*16 + (lane >> 2) + hf*8;
        int c = wn*32 + ni*8 + (lane & 3)*2;
        int i_ = R / L, k_ = R - i_ * L;
        *(float2*)&out[(k_*L + i_)*CD + c] =
            make_float2(acc[mi][ni][hf*2] + bo[c], acc[mi][ni][hf*2+1] + bo[c+1]);
    }
}

// ---------------- launch ----------------------------------------------------
extern "C" void kernel_launch(void* const* d_in, const int* in_sizes, int n_in,
                              void* d_out, int out_size)
{
    const float* pair      = (const float*)d_in[0];
    const float* bias      = (const float*)d_in[1];
    const float* ln_pair_w = (const float*)d_in[2];
    const float* ln_pair_b = (const float*)d_in[3];
    const float* ln_bias_w = (const float*)d_in[4];
    const float* ln_bias_b = (const float*)d_in[5];
    const float* Wq        = (const float*)d_in[6];
    const float* Wk        = (const float*)d_in[7];
    const float* Wv        = (const float*)d_in[8];
    const float* Wb        = (const float*)d_in[9];
    const float* Wg        = (const float*)d_in[10];
    const float* bg        = (const float*)d_in[11];
    const float* Wo        = (const float*)d_in[12];
    const float* bo        = (const float*)d_in[13];
    float* out = (float*)d_out;

    cudaFuncSetAttribute(proj_kernel, cudaFuncAttributeMaxDynamicSharedMemorySize, SMEM_BYTES);
    cudaFuncSetAttribute(attn_kernel, cudaFuncAttributeMaxDynamicSharedMemorySize, SMEM_BYTES);
    cudaFuncSetAttribute(out_kernel,  cudaFuncAttributeMaxDynamicSharedMemorySize, SMEM_BYTES);

    prep_weights  <<<320, 256>>>(Wq, Wk, Wv, Wg, Wo);
    ln_pair_kernel<<<RTOT, 128>>>(pair, ln_pair_w, ln_pair_b);
    bproj_kernel  <<<RTOT, 128>>>(bias, ln_bias_w, ln_bias_b, Wb);
    proj_kernel   <<<dim3(4, RTOT/128), 256, SMEM_BYTES>>>(bg);
    transp_v      <<<dim3(L/32, L, H), 128>>>();
    attn_kernel   <<<dim3(L/128, L/128, H*KSPL), 256, SMEM_BYTES>>>();
    softmax_kernel<<<H*L, 128>>>();
    out_kernel    <<<dim3(L*DH/128, L/128, H), 256, SMEM_BYTES>>>();
    final_kernel  <<<dim3(1, RTOT/128), 256>>>(bo, out);
}